// round 15
// baseline (speedup 1.0000x reference)
#include <cuda_runtime.h>
#include <cstdint>

// DimeNetPP radius-graph distances + triplet angles.
// TMA zero-fill from a SHARED constant zero buffer: each warp (one per
// molecule-row) issues one cp.async.bulk (9216 B of zeros) to its row's GMEM
// slab, overlaps the TMA with adjacency/dists compute, waits, then scatters
// only the ~55 symmetric triplet angles directly to GMEM. No per-row smem
// staging at all -> smem 13 KB/CTA, ~3x the occupancy of the staged version.
// Inputs: [0] atomic_ns (unused), [1] coords f32 [N,3], [2] batch_node_vec (unused)
// Output: f32, dists [B,48,48] then angles [B,48,48,48].

#define MOL_B 128
#define MM 48
#define THREADS 128
#define CTAS (MOL_B * MM / 4)    // 1536 CTAs x 4 warps = 6144 rows
#define CUTOFF_F 1.5f
#define TILE_F (MM * MM)         // 2304 floats = 9216 bytes

// Branch-free atan2 for y >= 0, (x,y) != (0,0). Max rel err ~1.3e-4.
__device__ __forceinline__ float fast_atan2_pos(float y, float x)
{
    const float ax = fabsf(x);
    const float mn = fminf(y, ax);
    const float mx = fmaxf(y, ax);
    const float t  = __fdividef(mn, mx);
    const float s  = t * t;
    float p = fmaf(s, 0.0208351f, -0.0851330f);
    p = fmaf(s, p, 0.1801410f);
    p = fmaf(s, p, -0.3302995f);
    p = fmaf(s, p, 0.9998660f);
    p = p * t;
    p = (y > ax) ? (1.57079632679f - p) : p;
    p = (x < 0.0f) ? (3.14159265359f - p) : p;
    return p;
}

__device__ __forceinline__ uint32_t smem_u32(const void* p)
{
    uint32_t a;
    asm("{ .reg .u64 t; cvta.to.shared.u64 t, %1; cvt.u32.u64 %0, t; }"
        : "=r"(a) : "l"(p));
    return a;
}

__global__ __launch_bounds__(THREADS)
void dimenet_kernel(const float* __restrict__ coords, float* __restrict__ out)
{
    const int tid  = threadIdx.x;
    const int wid  = tid >> 5;
    const int lane = tid & 31;
    const int row  = blockIdx.x * 4 + wid;           // 0 .. 6143
    const int b    = row / MM;                       // molecule
    const int j    = row - b * MM;                   // center row

    __shared__ float4 zbuf[TILE_F / 4];              // 9216 B, stays all-zero
    __shared__ float  nx[4][MM], ny[4][MM], nz[4][MM], nd2[4][MM];
    __shared__ int    nk[4][MM];

    // Zero the shared zero-buffer once (CTA-wide), then never write it again.
    {
        const float4 z = make_float4(0.f, 0.f, 0.f, 0.f);
        #pragma unroll
        for (int e = tid; e < TILE_F / 4; e += THREADS) zbuf[e] = z;
    }
    __syncthreads();

    const float* __restrict__ mc = coords + b * (MM * 3);
    float* __restrict__ dists  = out;
    float* __restrict__ angles = out + (size_t)MOL_B * MM * MM;
    float* const rowbase = angles + (size_t)row * TILE_F;

    // Issue the background zero-fill of this row's 9216-byte GMEM slab.
    if (lane == 0) {
        const uint32_t zsrc = smem_u32(&zbuf[0]);
        asm volatile("fence.proxy.async.shared::cta;" ::: "memory");
        asm volatile(
            "cp.async.bulk.global.shared::cta.bulk_group [%0], [%1], %2;"
            :: "l"(rowbase), "r"(zsrc), "r"((uint32_t)(TILE_F * 4)) : "memory");
        asm volatile("cp.async.bulk.commit_group;" ::: "memory");
    }

    // Overlap: adjacency + dists row + compacted neighbor vectors.
    const float px = __ldg(&mc[j * 3 + 0]);
    const float py = __ldg(&mc[j * 3 + 1]);
    const float pz = __ldg(&mc[j * 3 + 2]);
    const unsigned below = (1u << lane) - 1u;
    float* const drow = dists + ((size_t)b * MM + j) * MM;

    const int q0 = lane;
    const float vx0 = __ldg(&mc[q0 * 3 + 0]) - px;
    const float vy0 = __ldg(&mc[q0 * 3 + 1]) - py;
    const float vz0 = __ldg(&mc[q0 * 3 + 2]) - pz;
    const float d20 = vx0 * vx0 + vy0 * vy0 + vz0 * vz0;
    const float dist0 = sqrtf(d20);
    const bool adj0 = (q0 != j) && (dist0 < CUTOFF_F);
    drow[q0] = adj0 ? dist0 : 0.0f;
    const unsigned m0 = __ballot_sync(0xffffffffu, adj0);

    bool adj1 = false;
    const int q1 = lane + 32;
    float vx1 = 0.f, vy1 = 0.f, vz1 = 0.f, d21 = 0.f;
    if (lane < 16) {
        vx1 = __ldg(&mc[q1 * 3 + 0]) - px;
        vy1 = __ldg(&mc[q1 * 3 + 1]) - py;
        vz1 = __ldg(&mc[q1 * 3 + 2]) - pz;
        d21 = vx1 * vx1 + vy1 * vy1 + vz1 * vz1;
        const float dist1 = sqrtf(d21);
        adj1 = (q1 != j) && (dist1 < CUTOFF_F);
        drow[q1] = adj1 ? dist1 : 0.0f;
    }
    const unsigned m1 = __ballot_sync(0xffffffffu, adj1);

    const int c0 = __popc(m0);
    const int c  = c0 + __popc(m1);
    if (adj0) {
        const int s = __popc(m0 & below);
        nx[wid][s] = vx0; ny[wid][s] = vy0; nz[wid][s] = vz0;
        nd2[wid][s] = d20; nk[wid][s] = q0;
    }
    if (adj1) {
        const int s = c0 + __popc(m1 & below);
        nx[wid][s] = vx1; ny[wid][s] = vy1; nz[wid][s] = vz1;
        nd2[wid][s] = d21; nk[wid][s] = q1;
    }

    // Wait for this row's zero-fill to land, then order all lanes behind it.
    if (lane == 0)
        asm volatile("cp.async.bulk.wait_group 0;" ::: "memory");
    __syncwarp();   // also publishes the smem neighbor arrays warp-wide

    // Strict upper-triangle symmetric pairs -> compute + scatter both mirrors.
    const int T = (c * (c - 1)) >> 1;
    for (int g = lane; g < T; g += 32) {
        int pi = (int)((1.0f + sqrtf(fmaf(8.f, (float)g, 1.f))) * 0.5f);
        if ((pi * (pi - 1)) >> 1 > g) pi--;
        if ((pi * (pi + 1)) >> 1 <= g) pi++;
        const int ki = g - ((pi * (pi - 1)) >> 1);

        const float vix = nx[wid][pi], viy = ny[wid][pi], viz = nz[wid][pi];
        const float vkx = nx[wid][ki], vky = ny[wid][ki], vkz = nz[wid][ki];
        const float a  = vix * vkx + viy * vky + viz * vkz;
        const float b2 = fmaxf(nd2[wid][pi] * nd2[wid][ki] - a * a, 0.f);
        const float ang = fast_atan2_pos(sqrtf(b2), a);

        const int ii = nk[wid][pi];
        const int kk = nk[wid][ki];
        rowbase[ii * MM + kk] = ang;
        rowbase[kk * MM + ii] = ang;
    }
}

extern "C" void kernel_launch(void* const* d_in, const int* in_sizes, int n_in,
                              void* d_out, int out_size)
{
    const float* coords = (const float*)d_in[1];
    float* out = (float*)d_out;
    dimenet_kernel<<<CTAS, THREADS>>>(coords, out);
}